// round 1
// baseline (speedup 1.0000x reference)
#include <cuda_runtime.h>

// Involution: B=4 H=56 W=56 C=256, K=7 (pad 3), G=16, Cg=16, Cr=64, eps=1e-3
// Inputs (metadata order): x, w_reduce, gamma, beta, mean, var, w_span, b_span
//
// Structure:
//   K1: r_act[b][d][hw] = ReLU(BN(x @ w_reduce))  -> __device__ scratch (3.2MB),
//       stored d-major so K2 loads coalesced.
//   K2: per (ht,g,b) block: kgen tile = r_act @ w_span[:, g*49:(g+1)*49] + b_span,
//       kept in smem; then 7x7 involution against an x halo tile (aliased over
//       the dead r region). kgen (39MB) never touches DRAM.

#define HH 56
#define WW 56
#define CCH 256
#define CR 64
#define KK 49
#define GG 16
#define CGR 16
#define PIX_PER_B (HH * WW)          // 3136
#define NPIX (4 * PIX_PER_B)         // 12544

// scratch: r activations, layout [b][d][hw]
__device__ float g_r[4 * CR * PIX_PER_B];

// ---------------------------------------------------------------------------
// Kernel 1: fused 1x1 conv (C->Cr) + BN(inference) + ReLU
// 196 blocks x 256 threads; 64 pixels per block.
// smem: xs[64][260] (padded, 66560B) + ws4[256*16] float4 (65536B) = 132096B
// thread t: dc = t&3 (d-range dc*16..+15), p = t>>2 (pixel in tile)
// ---------------------------------------------------------------------------
__global__ void __launch_bounds__(256, 1)
k_reduce(const float* __restrict__ x,
         const float* __restrict__ w_reduce,
         const float* __restrict__ gamma,
         const float* __restrict__ beta,
         const float* __restrict__ mean,
         const float* __restrict__ var)
{
    extern __shared__ float sm1[];
    float*  xs  = sm1;                       // [64][260], padded rows
    float4* ws4 = (float4*)(sm1 + 64 * 260); // [256*16] quads: ws4[c*16+q] = w_reduce[c][4q..4q+3]

    const int t    = threadIdx.x;
    const int pix0 = blockIdx.x * 64;        // 3136 % 64 == 0 -> never straddles batch
    const int b    = pix0 / PIX_PER_B;
    const int hw0  = pix0 % PIX_PER_B;

    // stage x tile: 64 px * 256 ch, coalesced float4, padded smem rows (260 floats, 16B-aligned)
    {
        const float4* xg = (const float4*)(x + (size_t)pix0 * CCH);
        for (int i4 = t; i4 < 64 * 64; i4 += 256) {
            const int p = i4 >> 6, c4 = i4 & 63;
            *(float4*)(xs + p * 260 + c4 * 4) = xg[i4];
        }
    }
    // stage w_reduce (16384 floats)
    {
        const float4* wg = (const float4*)w_reduce;
        for (int i4 = t; i4 < 4096; i4 += 256) ws4[i4] = wg[i4];
    }
    __syncthreads();

    const int dc = t & 3;        // which 16-wide d chunk
    const int p  = t >> 2;       // pixel within tile

    float acc[16];
#pragma unroll
    for (int j = 0; j < 16; j++) acc[j] = 0.f;

    const float* xrow = xs + p * 260;
#pragma unroll 4
    for (int c = 0; c < 256; c++) {
        const float xv = xrow[c];
        const float4 w0 = ws4[c * 16 + dc * 4 + 0];
        const float4 w1 = ws4[c * 16 + dc * 4 + 1];
        const float4 w2 = ws4[c * 16 + dc * 4 + 2];
        const float4 w3 = ws4[c * 16 + dc * 4 + 3];
        acc[0]  += xv * w0.x;  acc[1]  += xv * w0.y;  acc[2]  += xv * w0.z;  acc[3]  += xv * w0.w;
        acc[4]  += xv * w1.x;  acc[5]  += xv * w1.y;  acc[6]  += xv * w1.z;  acc[7]  += xv * w1.w;
        acc[8]  += xv * w2.x;  acc[9]  += xv * w2.y;  acc[10] += xv * w2.z;  acc[11] += xv * w2.w;
        acc[12] += xv * w3.x;  acc[13] += xv * w3.y;  acc[14] += xv * w3.z;  acc[15] += xv * w3.w;
    }

    const int hw = hw0 + p;
#pragma unroll
    for (int j = 0; j < 16; j++) {
        const int d = dc * 16 + j;
        const float sc = __ldg(&gamma[d]) * rsqrtf(__ldg(&var[d]) + 1e-3f);
        float v = (acc[j] - __ldg(&mean[d])) * sc + __ldg(&beta[d]);
        v = fmaxf(v, 0.f);
        g_r[((size_t)b * CR + d) * PIX_PER_B + hw] = v;
    }
}

// ---------------------------------------------------------------------------
// Kernel 2: per (ht, g, b): span GEMM -> kgen in smem -> involution
// grid (14, 16, 4), 224 threads, 2 CTAs/SM.
// smem layout (113792B total):
//   [0      .. 57344)  sm_rx : r[64][224]  (phase A/B)  ALIASED with x[10][62][16] (phase C/D)
//   [57344  .. 69888)  sm_w  : w_span slice [64][49]
//   [69888  .. 113792) sm_kg : kgen [224][49]
// ---------------------------------------------------------------------------
__global__ void __launch_bounds__(224, 2)
k_inv(const float* __restrict__ x,
      const float* __restrict__ w_span,
      const float* __restrict__ b_span,
      float* __restrict__ out)
{
    extern __shared__ float sm2[];
    float* sm_rx = sm2;                 // r: [d][p] 64x224  /  later x halo: [10][62][16]
    float* sm_w  = sm2 + 64 * 224;      // [64][49]
    float* sm_kg = sm_w + 64 * 49;      // [224][49]

    const int t  = threadIdx.x;
    const int ht = blockIdx.x;          // 0..13 (4 rows each)
    const int g  = blockIdx.y;          // 0..15
    const int b  = blockIdx.z;          // 0..3
    const int hw0 = ht * 4 * WW;        // ht*224

    // ---- phase A: load r tile [64][224], coalesced float4, conflict-free smem writes
    for (int i4 = t; i4 < 64 * 56; i4 += 224) {
        const int d = i4 / 56, p4 = i4 % 56;
        const float4 v = *(const float4*)(g_r + ((size_t)(b * CR + d)) * PIX_PER_B + hw0 + p4 * 4);
        *(float4*)(sm_rx + d * 224 + p4 * 4) = v;
    }
    // load w_span slice for this group
    for (int i = t; i < 64 * 49; i += 224) {
        const int d = i / 49, k = i % 49;
        sm_w[i] = w_span[d * 784 + g * 49 + k];
    }
    __syncthreads();

    // ---- phase B: kgen GEMM  kg[p][k] = sum_d r[d][p] * w[d][k]
    // 224 thr = 32 (pixel dir, tp) x 7 (k dir, tk). Thread tile 7x7 (49 acc).
    const int tp = t & 31;              // lane
    const int tk = t >> 5;              // 0..6 (uniform per warp -> sm_w broadcast)

    float acc[7][7];
#pragma unroll
    for (int j = 0; j < 7; j++)
#pragma unroll
        for (int i = 0; i < 7; i++) acc[j][i] = 0.f;

#pragma unroll 2
    for (int d = 0; d < 64; d++) {
        float rv[7], wv[7];
#pragma unroll
        for (int j = 0; j < 7; j++) rv[j] = sm_rx[d * 224 + tp + 32 * j];
#pragma unroll
        for (int i = 0; i < 7; i++) wv[i] = sm_w[d * 49 + i * 7 + tk];
#pragma unroll
        for (int j = 0; j < 7; j++)
#pragma unroll
            for (int i = 0; i < 7; i++) acc[j][i] += rv[j] * wv[i];
    }

    // write kgen (+bias) to smem; banks (tp*17+k)%32 -> conflict-free
#pragma unroll
    for (int j = 0; j < 7; j++) {
        const int p = tp + 32 * j;
#pragma unroll
        for (int i = 0; i < 7; i++) {
            const int k = i * 7 + tk;
            sm_kg[p * 49 + k] = acc[j][i] + __ldg(&b_span[g * 49 + k]);
        }
    }
    __syncthreads();   // everyone done reading r -> safe to overwrite with x halo

    // ---- phase C: load x halo [rows ht*4-3 .. ht*4+6][cols -3..58][16 ch of group g]
    for (int idx = t; idx < 10 * 62 * 16; idx += 224) {
        const int c    = idx & 15;
        const int rest = idx >> 4;
        const int col  = rest % 62 - 3;
        const int row  = rest / 62 + ht * 4 - 3;
        float v = 0.f;
        if (row >= 0 && row < HH && col >= 0 && col < WW)
            v = x[((size_t)(b * HH + row) * WW + col) * CCH + g * CGR + c];
        sm_rx[idx] = v;
    }
    __syncthreads();

    // ---- phase D: involution. 224 thr = 16 ch x 14 pixel-groups; 16 px each.
    const int c  = t & 15;
    const int pg = t >> 4;              // 0..13
#pragma unroll 4
    for (int m = 0; m < 16; m++) {
        const int p  = pg * 16 + m;     // 0..223, row-major in tile
        const int i  = p / 56;
        const int jc = p % 56;
        const float* kgp = sm_kg + p * 49;        // broadcast across 16 lanes
        const float* xb  = sm_rx + (i * 62 + jc) * 16 + c;
        float a = 0.f;
#pragma unroll
        for (int kh = 0; kh < 7; kh++)
#pragma unroll
            for (int kw = 0; kw < 7; kw++)
                a += kgp[kh * 7 + kw] * xb[(kh * 62 + kw) * 16];
        out[((size_t)((b * HH + ht * 4 + i) * WW) + jc) * CCH + g * CGR + c] = a;
    }
}

// ---------------------------------------------------------------------------
extern "C" void kernel_launch(void* const* d_in, const int* in_sizes, int n_in,
                              void* d_out, int out_size)
{
    const float* x        = (const float*)d_in[0];
    const float* w_reduce = (const float*)d_in[1];
    const float* gamma    = (const float*)d_in[2];
    const float* beta     = (const float*)d_in[3];
    const float* mean     = (const float*)d_in[4];
    const float* var      = (const float*)d_in[5];
    const float* w_span   = (const float*)d_in[6];
    const float* b_span   = (const float*)d_in[7];
    float* out = (float*)d_out;

    const int smem1 = (64 * 260 + 256 * 64) * 4;               // 132096
    const int smem2 = (64 * 224 + 64 * 49 + 224 * 49) * 4;     // 113792
    cudaFuncSetAttribute(k_reduce, cudaFuncAttributeMaxDynamicSharedMemorySize, smem1);
    cudaFuncSetAttribute(k_inv,    cudaFuncAttributeMaxDynamicSharedMemorySize, smem2);

    k_reduce<<<NPIX / 64, 256, smem1>>>(x, w_reduce, gamma, beta, mean, var);
    k_inv<<<dim3(14, 16, 4), 224, smem2>>>(x, w_span, b_span, out);
}

// round 8
// speedup vs baseline: 1.9727x; 1.9727x over previous
#include <cuda_runtime.h>

// Involution: B=4 H=56 W=56 C=256, K=7 (pad 3), G=16, Cg=16, Cr=64, eps=1e-3
// Inputs: x, w_reduce, gamma, beta, mean, var, w_span, b_span
//
// K1: r[b][d][hw] = ReLU(BN(x @ w_reduce)) -> scratch (d-major), f32x2 math.
// K2: per (4-row tile, group, batch): span GEMM (f32x2, k-pairs) -> kgen in smem,
//     then 7x7 involution with channel-pair f32x2 accs against a float2 x-halo
//     (odd-stride 641 layout, conflict-free) aliased over the dead r/w smem.

#define HH 56
#define WW 56
#define CCH 256
#define CR 64
#define GG 16
#define PIX_PER_B (HH * WW)          // 3136
#define NPIX (4 * PIX_PER_B)         // 12544

typedef unsigned long long ull;

__device__ __forceinline__ ull f2pack(float a, float b) {
    ull r; asm("mov.b64 %0, {%1, %2};" : "=l"(r) : "f"(a), "f"(b)); return r;
}
__device__ __forceinline__ ull f2splat(float a) {
    ull r; asm("mov.b64 %0, {%1, %1};" : "=l"(r) : "f"(a)); return r;
}
__device__ __forceinline__ void f2unpack(ull v, float& a, float& b) {
    asm("mov.b64 {%0, %1}, %2;" : "=f"(a), "=f"(b) : "l"(v));
}
__device__ __forceinline__ ull f2fma(ull a, ull b, ull c) {
    ull d; asm("fma.rn.f32x2 %0, %1, %2, %3;" : "=l"(d) : "l"(a), "l"(b), "l"(c)); return d;
}

// scratch: r activations, layout [b][d][hw]
__device__ __align__(16) float g_r[4 * CR * PIX_PER_B];

// ---------------------------------------------------------------------------
// K1: 1x1 conv (256->64) + BN + ReLU.
// 196 blocks x 128 threads; 64 px x 64 d per block; thread tile 8px x 4d.
// k-chunked (64 c at a time): xs[64][66] + ws[64][68] = 34304B smem.
// xs staged as float2 (row stride 66 floats: 8B-aligned, and broadcast pairs in
// the compute loop land 16 banks apart -> conflict-free).
// ---------------------------------------------------------------------------
__global__ void __launch_bounds__(128, 6)
k_reduce(const float* __restrict__ x,
         const float* __restrict__ w_reduce,
         const float* __restrict__ gamma,
         const float* __restrict__ beta,
         const float* __restrict__ mean,
         const float* __restrict__ var)
{
    extern __shared__ float sm1[];
    float* xs = sm1;                 // [64][66]
    float* ws = sm1 + 64 * 66;       // [64][68]  ws[c][d]

    const int t    = threadIdx.x;
    const int pix0 = blockIdx.x * 64;
    const int b    = pix0 / PIX_PER_B;
    const int hw0  = pix0 % PIX_PER_B;

    const int dq = t & 15;           // d chunk: d = dq*4 + dd
    const int pq = t >> 4;           // 0..7 : pixels pq*8 .. pq*8+7

    ull acc2[8][2];
#pragma unroll
    for (int j = 0; j < 8; j++) { acc2[j][0] = 0ull; acc2[j][1] = 0ull; }

    const float2* xg2 = (const float2*)x;
    const float4* wg  = (const float4*)w_reduce;

    for (int c0 = 0; c0 < 256; c0 += 64) {
        if (c0) __syncthreads();
        // stage x chunk: 64 px x 64 c = 2048 float2 (8B-aligned stores)
#pragma unroll
        for (int it = 0; it < 16; it++) {
            const int i2 = t + it * 128;
            const int p = i2 >> 5, c2 = i2 & 31;
            *(float2*)(xs + p * 66 + c2 * 2) =
                xg2[(size_t)(pix0 + p) * 128 + (c0 >> 1) + c2];
        }
        // stage w chunk: 64 c x 64 d (1024 float4)
#pragma unroll
        for (int it = 0; it < 8; it++) {
            const int i4 = t + it * 128;
            const int c = i4 >> 4, d4 = i4 & 15;
            *(float4*)(ws + c * 68 + d4 * 4) = wg[(size_t)(c0 + c) * 16 + d4];
        }
        __syncthreads();

#pragma unroll 4
        for (int c = 0; c < 64; c++) {
            const float4 w = *(const float4*)(ws + c * 68 + dq * 4);
            const ull wlo = f2pack(w.x, w.y);
            const ull whi = f2pack(w.z, w.w);
#pragma unroll
            for (int j = 0; j < 8; j++) {
                const ull xp = f2splat(xs[(pq * 8 + j) * 66 + c]);
                acc2[j][0] = f2fma(xp, wlo, acc2[j][0]);
                acc2[j][1] = f2fma(xp, whi, acc2[j][1]);
            }
        }
    }

    // BN + ReLU epilogue, store d-major
    float sc[4], mn[4], bt[4];
#pragma unroll
    for (int dd = 0; dd < 4; dd++) {
        const int d = dq * 4 + dd;
        sc[dd] = __ldg(&gamma[d]) * rsqrtf(__ldg(&var[d]) + 1e-3f);
        mn[dd] = __ldg(&mean[d]);
        bt[dd] = __ldg(&beta[d]);
    }
#pragma unroll
    for (int j = 0; j < 8; j++) {
        float v[4];
        f2unpack(acc2[j][0], v[0], v[1]);
        f2unpack(acc2[j][1], v[2], v[3]);
        const int hw = hw0 + pq * 8 + j;
#pragma unroll
        for (int dd = 0; dd < 4; dd++) {
            const int d = dq * 4 + dd;
            float o = (v[dd] - mn[dd]) * sc[dd] + bt[dd];
            g_r[((size_t)(b * CR + d)) * PIX_PER_B + hw] = fmaxf(o, 0.f);
        }
    }
}

// ---------------------------------------------------------------------------
// K2: span GEMM + involution, grid (14,16,4), 224 threads, 2 CTAs/SM.
// smem (floats): sm_r [32][224] @0 (28672B) | sm_w [64][56] @7168 (14336B)
//                sm_kg [224][49] @10752 (43904B)      total 86912B
// x-halo (phase C/D) aliases [0..10752): float2 X2[c2*641 + rr*64 + col], 41KB.
// ---------------------------------------------------------------------------
#define R_OFF  0
#define W_OFF  7168
#define KG_OFF 10752
#define SM2_FLOATS 21728

__global__ void __launch_bounds__(224, 2)
k_inv(const float* __restrict__ x,
      const float* __restrict__ w_span,
      const float* __restrict__ b_span,
      float* __restrict__ out)
{
    extern __shared__ float sm2[];
    float* sm_r  = sm2 + R_OFF;
    float* sm_w  = sm2 + W_OFF;      // [d][kh*8 + kw]  (pad 7->8, row 56)
    float* sm_kg = sm2 + KG_OFF;     // [p][49]

    const int t  = threadIdx.x;
    const int ht = blockIdx.x;       // 0..13
    const int g  = blockIdx.y;       // 0..15
    const int b  = blockIdx.z;       // 0..3
    const int hw0 = ht * 4 * WW;

    // ---- load w_span slice once: sm_w[d][ (k/7)*8 + k%7 ] = w_span[d][g*49+k]
    for (int i = t; i < 64 * 49; i += 224) {
        const int d = i / 49, k = i % 49;
        sm_w[d * 56 + (k / 7) * 8 + (k % 7)] = w_span[(size_t)d * 784 + g * 49 + k];
    }

    // GEMM thread mapping: tp pixel lane, tk = kh (uniform per warp)
    const int tp = t & 31;
    const int tk = t >> 5;           // 0..6

    ull  acc2[7][3];                 // k pairs (tk*7 + {0,1},{2,3},{4,5})
    float accs[7];                   // k = tk*7 + 6
#pragma unroll
    for (int j = 0; j < 7; j++) {
        acc2[j][0] = acc2[j][1] = acc2[j][2] = 0ull; accs[j] = 0.f;
    }

    // ---- two d-halves: load r[32][224], accumulate
    for (int d0 = 0; d0 < 64; d0 += 32) {
        __syncthreads();             // prev-phase readers done (also orders w load)
#pragma unroll
        for (int it = 0; it < 8; it++) {
            const int i4 = t + it * 224;
            const int d = i4 / 56, p4 = i4 % 56;
            *(float4*)(sm_r + d * 224 + p4 * 4) =
                *(const float4*)(g_r + ((size_t)(b * CR + d0 + d)) * PIX_PER_B + hw0 + p4 * 4);
        }
        __syncthreads();

#pragma unroll 2
        for (int d = 0; d < 32; d++) {
            const float* rrow = sm_r + d * 224 + tp;
            const float* wrow = sm_w + (d0 + d) * 56 + tk * 8;
            const ull wp0 = *(const ull*)(wrow);
            const ull wp1 = *(const ull*)(wrow + 2);
            const ull wp2 = *(const ull*)(wrow + 4);
            const float w6 = wrow[6];
#pragma unroll
            for (int j = 0; j < 7; j++) {
                const float rv = rrow[32 * j];
                const ull rp = f2splat(rv);
                acc2[j][0] = f2fma(rp, wp0, acc2[j][0]);
                acc2[j][1] = f2fma(rp, wp1, acc2[j][1]);
                acc2[j][2] = f2fma(rp, wp2, acc2[j][2]);
                accs[j] += rv * w6;
            }
        }
    }

    // ---- write kgen (+bias) to smem
    float bv[7];
#pragma unroll
    for (int i = 0; i < 7; i++) bv[i] = __ldg(&b_span[g * 49 + tk * 7 + i]);
#pragma unroll
    for (int j = 0; j < 7; j++) {
        const int p = tp + 32 * j;
        float* kgp = sm_kg + p * 49 + tk * 7;
#pragma unroll
        for (int q = 0; q < 3; q++) {
            float lo, hi; f2unpack(acc2[j][q], lo, hi);
            kgp[2 * q]     = lo + bv[2 * q];
            kgp[2 * q + 1] = hi + bv[2 * q + 1];
        }
        kgp[6] = accs[j] + bv[6];
    }
    __syncthreads();   // r & w dead; kg complete

    // ---- phase C: x halo as float2, layout X2[c2*641 + rr*64 + col]
    // halo rows rr 0..9 <-> global row ht*4-3+rr ; cols col 0..61 <-> global col-3
    ull* X2 = (ull*)sm2;
    for (int idx = t; idx < 8 * 10 * 62; idx += 224) {
        const int c2 = idx & 7;
        const int r2 = idx >> 3;
        const int col = r2 % 62;
        const int rr  = r2 / 62;
        const int grow = ht * 4 - 3 + rr;
        const int gcol = col - 3;
        ull v = 0ull;
        if (grow >= 0 && grow < HH && gcol >= 0 && gcol < WW)
            v = *(const ull*)(x + ((size_t)((b * HH + grow) * WW + gcol)) * CCH + g * 16 + c2 * 2);
        X2[c2 * 641 + rr * 64 + col] = v;
    }
    __syncthreads();

    // ---- phase D: involution. thread = (c2 channel-pair, cg col-group, ii row)
    const int c2 = t & 7;
    const int rgrp = t >> 3;         // 0..27
    const int cg = rgrp % 7;         // col group: cols cg*8 .. +7
    const int ii = rgrp / 7;         // row in tile 0..3

    ull acc[8];
#pragma unroll
    for (int m = 0; m < 8; m++) acc[m] = 0ull;

    const int xbase = c2 * 641 + ii * 64 + cg * 8;
    const float* kgbase = sm_kg + (ii * 56 + cg * 8) * 49;

#pragma unroll 1
    for (int kh = 0; kh < 7; kh++) {
        ull xw[14];
        const ull* xr = X2 + xbase + kh * 64;
#pragma unroll
        for (int u = 0; u < 14; u++) xw[u] = xr[u];
        const float* kgh = kgbase + kh * 7;
#pragma unroll
        for (int m = 0; m < 8; m++) {
            const float* kp = kgh + m * 49;
#pragma unroll
            for (int kw = 0; kw < 7; kw++)
                acc[m] = f2fma(f2splat(kp[kw]), xw[m + kw], acc[m]);
        }
    }

    const size_t obase = ((size_t)((b * HH + ht * 4 + ii) * WW + cg * 8)) * CCH + g * 16 + c2 * 2;
#pragma unroll
    for (int m = 0; m < 8; m++) {
        float lo, hi; f2unpack(acc[m], lo, hi);
        *(float2*)(out + obase + (size_t)m * CCH) = make_float2(lo, hi);
    }
}

// ---------------------------------------------------------------------------
extern "C" void kernel_launch(void* const* d_in, const int* in_sizes, int n_in,
                              void* d_out, int out_size)
{
    const float* x        = (const float*)d_in[0];
    const float* w_reduce = (const float*)d_in[1];
    const float* gamma    = (const float*)d_in[2];
    const float* beta     = (const float*)d_in[3];
    const float* mean     = (const float*)d_in[4];
    const float* var      = (const float*)d_in[5];
    const float* w_span   = (const float*)d_in[6];
    const float* b_span   = (const float*)d_in[7];
    float* out = (float*)d_out;

    const int smem1 = (64 * 66 + 64 * 68) * 4;   // 34304
    const int smem2 = SM2_FLOATS * 4;            // 86912
    cudaFuncSetAttribute(k_reduce, cudaFuncAttributeMaxDynamicSharedMemorySize, smem1);
    cudaFuncSetAttribute(k_inv,    cudaFuncAttributeMaxDynamicSharedMemorySize, smem2);

    k_reduce<<<NPIX / 64, 128, smem1>>>(x, w_reduce, gamma, beta, mean, var);
    k_inv<<<dim3(14, 16, 4), 224, smem2>>>(x, w_span, b_span, out);
}